// round 16
// baseline (speedup 1.0000x reference)
#include <cuda_runtime.h>
#include <cstdint>

// Fixed shapes: points (4, 8192, 3) fp32
#define BATCH     4
#define NPTS      8192
#define NTOT      (BATCH * NPTS)
#define NN_SIZE   16
#define RADIUS2   0.25f
#define EPS_LOSS  1e-4f

// Spatial grid: cell width 0.25, domain [-5,5) clamped
#define GDIM      40
#define NCELLS    (GDIM * GDIM * GDIM)     // 64000 per batch
#define GMIN      (-5.0f)
#define INV_CW    4.0f
#define CW        0.25f

// Hierarchical scan: 256 segments x 250 cells per batch
#define NSEG      256
#define SEGC      (NCELLS / NSEG)          // 250
#define SCAN_T    128
#define SCAN_W    (SCAN_T / 32)            // 4 warps
#define SCAN_WMASK ((1u << SCAN_W) - 1u)   // 0xF

// Main kernel: one WARP per query
#define TPB       256
#define WPB       (TPB / 32)               // 8 queries per block
#define BPB       (NPTS / WPB)             // 1024 blocks per batch
#define NBLK      (BATCH * BPB)            // 4096
#define CAP       512                      // gathered candidates per warp

// All zero at module load; self-restored every run for graph replay.
__device__ int      g_count [BATCH * NCELLS];
__device__ int      g_start [BATCH * NCELLS];  // excl prefix; becomes END after scatter
__device__ int      g_part  [BATCH * NSEG];
__device__ float4   g_sorted[NTOT + 32];       // +pad for unconditional lane loads
__device__ int      g_sid   [NTOT];
__device__ float    g_loss  [NTOT];
__device__ unsigned g_done;

__device__ __forceinline__ int cell_of(float x, float y, float z) {
    int cx = (int)floorf((x - GMIN) * INV_CW);
    int cy = (int)floorf((y - GMIN) * INV_CW);
    int cz = (int)floorf((z - GMIN) * INV_CW);
    cx = min(max(cx, 0), GDIM - 1);
    cy = min(max(cy, 0), GDIM - 1);
    cz = min(max(cz, 0), GDIM - 1);
    return (cz * GDIM + cy) * GDIM + cx;
}

__global__ void k_count(const float* __restrict__ pts) {
    int i = blockIdx.x * blockDim.x + threadIdx.x;
    if (i >= NTOT) return;
    int b = i >> 13;
    float x = pts[3 * i + 0], y = pts[3 * i + 1], z = pts[3 * i + 2];
    atomicAdd(&g_count[b * NCELLS + cell_of(x, y, z)], 1);
}

__global__ __launch_bounds__(SCAN_T) void k_scanA() {
    __shared__ int red[SCAN_T];
    const int blk = blockIdx.x;
    const int t   = threadIdx.x;
    const int base = (blk / NSEG) * NCELLS + (blk % NSEG) * SEGC;
    int s = 0;
    for (int i = t; i < SEGC; i += SCAN_T) s += g_count[base + i];
    red[t] = s;
    __syncthreads();
#pragma unroll
    for (int off = SCAN_T / 2; off > 0; off >>= 1) {
        if (t < off) red[t] += red[t + off];
        __syncthreads();
    }
    if (t == 0) g_part[blk] = red[0];
}

__global__ __launch_bounds__(256) void k_scanB() {
    __shared__ int wsum[8];
    const int b = blockIdx.x;
    const int t = threadIdx.x;
    const int lane = t & 31, warp = t >> 5;
    int v = g_part[b * NSEG + t];
    int inc = v;
#pragma unroll
    for (int off = 1; off < 32; off <<= 1) {
        int n = __shfl_up_sync(0xffffffffu, inc, off);
        if (lane >= off) inc += n;
    }
    if (lane == 31) wsum[warp] = inc;
    __syncthreads();
    if (warp == 0 && lane < 8) {
        int w = wsum[lane];
#pragma unroll
        for (int off = 1; off < 8; off <<= 1) {
            int n = __shfl_up_sync(0xffu, w, off);
            if (lane >= off) w += n;
        }
        wsum[lane] = w;
    }
    __syncthreads();
    g_part[b * NSEG + t] = inc - v + (warp ? wsum[warp - 1] : 0);
}

__global__ __launch_bounds__(SCAN_T) void k_scanC() {
    __shared__ int wsum[SCAN_W];
    const int blk = blockIdx.x;
    const int t   = threadIdx.x;
    const int lane = t & 31, warp = t >> 5;
    const int base = (blk / NSEG) * NCELLS + (blk % NSEG) * SEGC;
    const int goff = g_part[blk];

    int v0 = (2 * t     < SEGC) ? g_count[base + 2 * t]     : 0;
    int v1 = (2 * t + 1 < SEGC) ? g_count[base + 2 * t + 1] : 0;
    int tot = v0 + v1;
    int inc = tot;
#pragma unroll
    for (int off = 1; off < 32; off <<= 1) {
        int n = __shfl_up_sync(0xffffffffu, inc, off);
        if (lane >= off) inc += n;
    }
    if (lane == 31) wsum[warp] = inc;
    __syncthreads();
    if (warp == 0 && lane < SCAN_W) {
        int w = wsum[lane];
#pragma unroll
        for (int off = 1; off < SCAN_W; off <<= 1) {
            int n = __shfl_up_sync(SCAN_WMASK, w, off);
            if (lane >= off) w += n;
        }
        wsum[lane] = w;
    }
    __syncthreads();
    int excl = goff + inc - tot + (warp ? wsum[warp - 1] : 0);
    if (2 * t < SEGC) {
        g_start[base + 2 * t] = excl;
        g_count[base + 2 * t] = 0;
    }
    if (2 * t + 1 < SEGC) {
        g_start[base + 2 * t + 1] = excl + v0;
        g_count[base + 2 * t + 1] = 0;
    }
}

__global__ void k_scatter(const float* __restrict__ pts) {
    int i = blockIdx.x * blockDim.x + threadIdx.x;
    if (i >= NTOT) return;
    int b = i >> 13;
    float x = pts[3 * i + 0], y = pts[3 * i + 1], z = pts[3 * i + 2];
    int c = cell_of(x, y, z);
    int pos = atomicAdd(&g_start[b * NCELLS + c], 1);
    float w = 0.5f * (x * x + y * y + z * z);
    g_sorted[b * NPTS + pos] = make_float4(x, y, z, w);
    g_sid[b * NPTS + pos] = i - b * NPTS;
}

// Branchless sorted insert (fallback path only).
__device__ __forceinline__ void sorted_insert16(float (&a)[16], float v) {
#pragma unroll
    for (int k = 15; k > 0; --k) {
        a[k] = fminf(fmaxf(v, a[k - 1]), a[k]);
    }
    a[0] = fminf(a[0], v);
}

__global__ __launch_bounds__(TPB) void k_main(float* __restrict__ out) {
    __shared__ float se[WPB][CAP];         // 16 KB: per-warp gathered e values
    __shared__ int   last_s;

    const int lane = threadIdx.x & 31;
    const int w    = threadIdx.x >> 5;
    const int b    = blockIdx.x / BPB;
    // Heavy-first permutation over per-batch block index.
    const int i    = blockIdx.x % BPB;
    const int blkq = (i & 1) ? (BPB / 2 + (i >> 1)) : (BPB / 2 - 1 - (i >> 1));
    const int g    = blkq * WPB + w;        // sorted query position (batch-rel)

    const float4* __restrict__ spts = &g_sorted[b * NPTS];
    const int*    __restrict__ cend = &g_start[b * NCELLS];
    float* mye = se[w];

    const unsigned FULL = 0xffffffffu;
    const unsigned ltmask = (1u << lane) - 1u;

    const float4 qp = spts[g];
    const float nqx = -qp.x, nqy = -qp.y, nqz = -qp.z;
    const float ecap = 0.5f * RADIUS2 - qp.w;   // e < ecap <=> d^2 < R^2

    int cx = (int)floorf((qp.x - GMIN) * INV_CW);
    int cy = (int)floorf((qp.y - GMIN) * INV_CW);
    int cz = (int)floorf((qp.z - GMIN) * INV_CW);
    cx = min(max(cx, 0), GDIM - 1);
    cy = min(max(cy, 0), GDIM - 1);
    cz = min(max(cz, 0), GDIM - 1);

    // Per-lane row setup: lane r (r<25) owns row (dz,dy) = (r/5-2, r%5-2).
    // All cend loads for all 25 rows issue in parallel across lanes.
    int ka = 0, kb = 0;
    if (lane < 25) {
        int nz = cz + lane / 5 - 2;
        int ny = cy + lane % 5 - 2;
        bool ok = ((unsigned)nz < GDIM) && ((unsigned)ny < GDIM);
        float zlo = GMIN + (float)nz * CW;
        float zd  = fmaxf(0.0f, fmaxf(zlo - qp.z, qp.z - (zlo + CW)));
        float ylo = GMIN + (float)ny * CW;
        float yd  = fmaxf(0.0f, fmaxf(ylo - qp.y, qp.y - (ylo + CW)));
        float yz2 = fmaf(zd, zd, yd * yd);
        ok = ok && (yz2 < RADIUS2 + 1e-5f);          // exact row prune
        float xr = sqrtf(fmaxf(RADIUS2 - yz2, 0.0f)) + 1e-3f;  // over-incl. safe
        int xa = max((int)floorf((qp.x - xr - GMIN) * INV_CW), 0);
        int xb = min((int)floorf((qp.x + xr - GMIN) * INV_CW), GDIM - 1);
        ok = ok && (xa <= xb);
        if (ok) {
            int row = (nz * GDIM + ny) * GDIM;
            int c0  = row + xa;
            ka = (c0 == 0) ? 0 : cend[c0 - 1];
            kb = cend[row + xb];
        }
    }

    // Gather pass: compact all in-radius e values into mye[0..cnt).
    int cnt = 0;
#pragma unroll 1
    for (int r = 0; r < 25; ++r) {
        int k0 = __shfl_sync(FULL, ka, r);
        int k1 = __shfl_sync(FULL, kb, r);
        for (int base = k0; base < k1; base += 32) {
            int k = base + lane;
            float4 cd = spts[k];                     // padded, unconditional
            float e = fmaf(cd.x, nqx, fmaf(cd.y, nqy, fmaf(cd.z, nqz, cd.w)));
            bool pred = (k < k1) && (e < ecap) && (k != g);
            unsigned m = __ballot_sync(FULL, pred);
            if (pred) {
                int pos = cnt + __popc(m & ltmask);
                if (pos < CAP) mye[pos] = e;
            }
            cnt += __popc(m);
        }
    }
    __syncwarp();

    float psum = 0.0f;
    if (cnt <= NN_SIZE) {
        // Light (~75%): loss = sum over ALL in-radius neighbors.
        if (lane < cnt) {
            psum = rsqrtf(fmaf(2.0f, qp.w + mye[lane], EPS_LOSS));
        }
    } else if (cnt <= CAP) {
        // Heavy: branchless stable rank selection of the 16 smallest.
        for (int j = lane; j < cnt; j += 32) {
            float vj = mye[j];
            int rank = 0;
            for (int q = 0; q < cnt; ++q) {
                float vq = mye[q];
                rank += (vq < vj) || (vq == vj && q < j);
            }
            if (rank < NN_SIZE) {
                psum += rsqrtf(fmaf(2.0f, qp.w + vj, EPS_LOSS));
            }
        }
    } else {
        // Fallback (practically unreachable; warp-uniform): per-lane top-16,
        // dump 512 values, rank-select among them.
        float a[16];
#pragma unroll
        for (int k2 = 0; k2 < 16; ++k2) a[k2] = ecap;
#pragma unroll 1
        for (int r = 0; r < 25; ++r) {
            int k0 = __shfl_sync(FULL, ka, r);
            int k1 = __shfl_sync(FULL, kb, r);
            for (int k = k0 + lane; k < k1; k += 32) {
                float4 cd = spts[k];
                float e = fmaf(cd.x, nqx, fmaf(cd.y, nqy, fmaf(cd.z, nqz, cd.w)));
                if (e < a[15] && k != g) sorted_insert16(a, e);
            }
        }
#pragma unroll
        for (int k2 = 0; k2 < 16; ++k2) mye[lane * 16 + k2] = a[k2];
        __syncwarp();
        for (int j = lane; j < CAP; j += 32) {
            float vj = mye[j];
            if (vj < ecap) {
                int rank = 0;
                for (int q = 0; q < CAP; ++q) {
                    float vq = mye[q];
                    rank += (vq < vj) || (vq == vj && q < j);
                }
                if (rank < NN_SIZE) {
                    psum += rsqrtf(fmaf(2.0f, qp.w + vj, EPS_LOSS));
                }
            }
        }
    }

    // Warp reduce + store per original index.
#pragma unroll
    for (int off = 16; off; off >>= 1) {
        psum += __shfl_xor_sync(FULL, psum, off);
    }
    if (lane == 0) {
        int oid = g_sid[b * NPTS + g];
        g_loss[b * NPTS + oid] = psum;
    }

    // Last-block fixed-order final reduction (proven R11/R12/R15).
    __threadfence();
    __syncthreads();
    if (threadIdx.x == 0) {
        unsigned ticket = atomicAdd(&g_done, 1u);
        last_s = (ticket == NBLK - 1) ? 1 : 0;
    }
    __syncthreads();
    if (last_s) {
        __shared__ float r[TPB];
        const int t = threadIdx.x;
        float sum = 0.0f;
#pragma unroll
        for (int j = 0; j < NTOT / TPB; ++j) {
            sum += g_loss[j * TPB + t];
        }
        r[t] = sum;
        __syncthreads();
#pragma unroll
        for (int off = TPB / 2; off > 0; off >>= 1) {
            if (t < off) r[t] += r[t + off];
            __syncthreads();
        }
        if (t == 0) {
            out[0] = r[0] * (1.0f / (float)(NTOT * NN_SIZE));
            g_done = 0;                     // self-restore for next replay
        }
    }
}

extern "C" void kernel_launch(void* const* d_in, const int* in_sizes, int n_in,
                              void* d_out, int out_size) {
    (void)in_sizes; (void)n_in; (void)out_size;
    const float* pts = (const float*)d_in[0];
    float* out = (float*)d_out;

    k_count  <<<(NTOT + 255) / 256, 256>>>(pts);   // idx 0
    k_scanA  <<<BATCH * NSEG, SCAN_T>>>();         // idx 1
    k_scanB  <<<BATCH, NSEG>>>();                  // idx 2
    k_scanC  <<<BATCH * NSEG, SCAN_T>>>();         // idx 3
    k_scatter<<<(NTOT + 255) / 256, 256>>>(pts);   // idx 4
    k_main   <<<NBLK, TPB>>>(out);                 // idx 5
}

// round 17
// speedup vs baseline: 2.6076x; 2.6076x over previous
#include <cuda_runtime.h>
#include <cstdint>

// Fixed shapes: points (4, 8192, 3) fp32
#define BATCH     4
#define NPTS      8192
#define NTOT      (BATCH * NPTS)
#define NN_SIZE   16
#define RADIUS2   0.25f
#define EPS_LOSS  1e-4f

// Spatial grid: cell width 0.25, domain [-5,5) clamped
#define GDIM      40
#define NCELLS    (GDIM * GDIM * GDIM)     // 64000 per batch
#define GMIN      (-5.0f)
#define INV_CW    4.0f
#define CW        0.25f

// Hierarchical scan: 500 segments x 128 cells per batch (one cell per thread)
#define NSEG      500
#define SEGC      128
#define SCAN_T    128
#define SCAN_W    (SCAN_T / 32)            // 4 warps
#define SCAN_WMASK ((1u << SCAN_W) - 1u)   // 0xF — matches participating lanes

// Main kernel layout (R15 proven)
#define SPLIT     4
#define TPB       128
#define QPB       (TPB / SPLIT)            // 32 queries per block
#define BPB       (NPTS / QPB)             // 256 blocks per batch
#define NBLK      (BATCH * BPB)            // 1024
#define MROW      65

// All zero at module load; self-restored every run for graph replay.
__device__ int      g_count [BATCH * NCELLS];
__device__ int      g_start [BATCH * NCELLS];  // excl prefix; becomes END after scatter
__device__ int      g_part  [BATCH * NSEG];    // segment totals
__device__ float4   g_sorted[NTOT + 16];       // +pad
__device__ int      g_sid   [NTOT];
__device__ float    g_loss  [NTOT];
__device__ unsigned g_done;

__device__ __forceinline__ int cell_of(float x, float y, float z) {
    int cx = (int)floorf((x - GMIN) * INV_CW);
    int cy = (int)floorf((y - GMIN) * INV_CW);
    int cz = (int)floorf((z - GMIN) * INV_CW);
    cx = min(max(cx, 0), GDIM - 1);
    cy = min(max(cy, 0), GDIM - 1);
    cz = min(max(cz, 0), GDIM - 1);
    return (cz * GDIM + cy) * GDIM + cx;
}

__global__ void k_count(const float* __restrict__ pts) {
    int i = blockIdx.x * blockDim.x + threadIdx.x;
    if (i >= NTOT) return;
    int b = i >> 13;
    float x = pts[3 * i + 0], y = pts[3 * i + 1], z = pts[3 * i + 2];
    atomicAdd(&g_count[b * NCELLS + cell_of(x, y, z)], 1);
}

// Segment totals: one block per (batch, segment); one cell per thread.
__global__ __launch_bounds__(SCAN_T) void k_scanA() {
    __shared__ int red[SCAN_T];
    const int blk = blockIdx.x;               // 0..BATCH*NSEG-1
    const int t   = threadIdx.x;
    const int base = (blk / NSEG) * NCELLS + (blk % NSEG) * SEGC;
    red[t] = g_count[base + t];
    __syncthreads();
#pragma unroll
    for (int off = SCAN_T / 2; off > 0; off >>= 1) {
        if (t < off) red[t] += red[t + off];
        __syncthreads();
    }
    if (t == 0) g_part[blk] = red[0];
}

// Per-segment exclusive scan. Each block redundantly computes its own
// segment-prefix (sum of preceding g_part) — removes the scanB launch.
__global__ __launch_bounds__(SCAN_T) void k_scanC() {
    __shared__ int red[SCAN_T];
    __shared__ int wsum[SCAN_W];
    const int blk = blockIdx.x;
    const int b   = blk / NSEG;
    const int seg = blk % NSEG;
    const int t   = threadIdx.x;
    const int lane = t & 31, warp = t >> 5;
    const int base = b * NCELLS + seg * SEGC;

    // Segment prefix: lane-strided sum of g_part[b*NSEG .. b*NSEG+seg-1].
    int pref = 0;
    for (int j = t; j < seg; j += SCAN_T) pref += g_part[b * NSEG + j];
    red[t] = pref;
    __syncthreads();
#pragma unroll
    for (int off = SCAN_T / 2; off > 0; off >>= 1) {
        if (t < off) red[t] += red[t + off];
        __syncthreads();
    }
    const int goff = red[0];
    __syncthreads();

    // 128-wide exclusive scan of this segment's cell counts.
    int v = g_count[base + t];
    int inc = v;
#pragma unroll
    for (int off = 1; off < 32; off <<= 1) {
        int n = __shfl_up_sync(0xffffffffu, inc, off);
        if (lane >= off) inc += n;
    }
    if (lane == 31) wsum[warp] = inc;
    __syncthreads();
    if (warp == 0 && lane < SCAN_W) {
        int w = wsum[lane];
#pragma unroll
        for (int off = 1; off < SCAN_W; off <<= 1) {
            int n = __shfl_up_sync(SCAN_WMASK, w, off);
            if (lane >= off) w += n;
        }
        wsum[lane] = w;
    }
    __syncthreads();
    int excl = goff + inc - v + (warp ? wsum[warp - 1] : 0);
    g_start[base + t] = excl;
    g_count[base + t] = 0;                   // self-restore for next replay
}

// Scatter; atomic consume of g_start turns it into the END-offset array.
__global__ void k_scatter(const float* __restrict__ pts) {
    int i = blockIdx.x * blockDim.x + threadIdx.x;
    if (i >= NTOT) return;
    int b = i >> 13;
    float x = pts[3 * i + 0], y = pts[3 * i + 1], z = pts[3 * i + 2];
    int c = cell_of(x, y, z);
    int pos = atomicAdd(&g_start[b * NCELLS + c], 1);
    float w = 0.5f * (x * x + y * y + z * z);
    g_sorted[b * NPTS + pos] = make_float4(x, y, z, w);
    g_sid[b * NPTS + pos] = i - b * NPTS;
}

// Branchless sorted insert (ascending), drop a[15].
__device__ __forceinline__ void sorted_insert16(float (&a)[16], float v) {
#pragma unroll
    for (int k = 15; k > 0; --k) {
        a[k] = fminf(fmaxf(v, a[k - 1]), a[k]);
    }
    a[0] = fminf(a[0], v);
}

// 2x-unrolled run scan; SELF check only on the center row.
template <bool SELF>
__device__ __forceinline__ void scan_run(const float4* __restrict__ spts,
                                         int k0, int k1, int s, int g,
                                         float nqx, float nqy, float nqz,
                                         float (&a)[16]) {
    int k = k0 + s;
    for (; k + SPLIT < k1; k += 2 * SPLIT) {
        float4 c0 = spts[k];
        float4 c1 = spts[k + SPLIT];
        float e0 = fmaf(c0.x, nqx, fmaf(c0.y, nqy, fmaf(c0.z, nqz, c0.w)));
        float e1 = fmaf(c1.x, nqx, fmaf(c1.y, nqy, fmaf(c1.z, nqz, c1.w)));
        bool ok0 = e0 < a[15], ok1 = e1 < a[15];
        if (SELF) { ok0 = ok0 && (k != g); ok1 = ok1 && (k + SPLIT != g); }
        if (ok0) sorted_insert16(a, e0);
        if (ok1) sorted_insert16(a, e1);
    }
    if (k < k1) {
        float4 c0 = spts[k];
        float e0 = fmaf(c0.x, nqx, fmaf(c0.y, nqy, fmaf(c0.z, nqz, c0.w)));
        bool ok0 = e0 < a[15];
        if (SELF) ok0 = ok0 && (k != g);
        if (ok0) sorted_insert16(a, e0);
    }
}

__global__ __launch_bounds__(TPB) void k_main(float* __restrict__ out) {
    __shared__ float mbuf[QPB * MROW];     // 8.3 KB
    __shared__ float qw_s[QPB];
    __shared__ int   last_s;

    const int t  = threadIdx.x;
    const int ql = t >> 2;
    const int s  = t & 3;
    const int b  = blockIdx.x / BPB;
    const int i  = blockIdx.x % BPB;
    const int blkq = (i & 1) ? (BPB / 2 + (i >> 1)) : (BPB / 2 - 1 - (i >> 1));
    const int g  = blkq * QPB + ql;

    const float4* __restrict__ spts = &g_sorted[b * NPTS];
    const int*    __restrict__ cend = &g_start[b * NCELLS];

    const float4 qp = spts[g];
    const float nqx = -qp.x, nqy = -qp.y, nqz = -qp.z;
    const float ecap = 0.5f * RADIUS2 - qp.w;
    if (s == 0) qw_s[ql] = qp.w;

    float a[16];
#pragma unroll
    for (int k = 0; k < 16; ++k) a[k] = ecap;

    int cx = (int)floorf((qp.x - GMIN) * INV_CW);
    int cy = (int)floorf((qp.y - GMIN) * INV_CW);
    int cz = (int)floorf((qp.z - GMIN) * INV_CW);
    cx = min(max(cx, 0), GDIM - 1);
    cy = min(max(cy, 0), GDIM - 1);
    cz = min(max(cz, 0), GDIM - 1);

    const int ORD[5] = {0, -1, 1, -2, 2};

#pragma unroll 1
    for (int jz = 0; jz < 5; ++jz) {
        int nz = cz + ORD[jz];
        if ((unsigned)nz >= GDIM) continue;
        float zlo = GMIN + (float)nz * CW;
        float zd  = fmaxf(0.0f, fmaxf(zlo - qp.z, qp.z - (zlo + CW)));
        float zd2 = zd * zd;
        if (zd2 >= RADIUS2 + 1e-5f) continue;

        int ka[5], kb[5];
#pragma unroll
        for (int jy = 0; jy < 5; ++jy) {
            int ny = cy + ORD[jy];
            bool ok = ((unsigned)ny < GDIM);
            float ylo = GMIN + (float)ny * CW;
            float yd  = fmaxf(0.0f, fmaxf(ylo - qp.y, qp.y - (ylo + CW)));
            float yz2 = fmaf(yd, yd, zd2);
            ok = ok && (yz2 < RADIUS2 + 1e-5f);
            float xr = sqrtf(fmaxf(RADIUS2 - yz2, 0.0f)) + 1e-3f;
            int xa = max((int)floorf((qp.x - xr - GMIN) * INV_CW), 0);
            int xb = min((int)floorf((qp.x + xr - GMIN) * INV_CW), GDIM - 1);
            ok = ok && (xa <= xb);
            int row = (nz * GDIM + ((unsigned)ny < GDIM ? ny : 0)) * GDIM;
            int c0  = row + xa;
            ka[jy] = ok ? ((c0 == 0) ? 0 : cend[c0 - 1]) : 0;
            kb[jy] = ok ? cend[row + xb] : 0;
        }
        if (jz == 0) {
            // center row (jy==0) contains self
            scan_run<true >(spts, ka[0], kb[0], s, g, nqx, nqy, nqz, a);
#pragma unroll
            for (int jy = 1; jy < 5; ++jy)
                scan_run<false>(spts, ka[jy], kb[jy], s, g, nqx, nqy, nqz, a);
        } else {
#pragma unroll
            for (int jy = 0; jy < 5; ++jy)
                scan_run<false>(spts, ka[jy], kb[jy], s, g, nqx, nqy, nqz, a);
        }
    }

#pragma unroll
    for (int k = 0; k < 16; ++k) {
        mbuf[ql * MROW + (s << 4) + k] = a[k];
    }
    __syncthreads();

    if (t < QPB) {
        const float* L   = &mbuf[t * MROW];
        const float  w   = qw_s[t];
        const float  cap = 0.5f * RADIUS2 - w;
        float part = 0.0f;
        int p0 = 0, p1 = 16, p2 = 32, p3 = 48;
#pragma unroll 1
        for (int it = 0; it < NN_SIZE; ++it) {
            float h0 = L[p0], h1 = L[p1], h2 = L[p2], h3 = L[p3];
            float m = fminf(fminf(h0, h1), fminf(h2, h3));
            if (m >= cap) break;
            part += rsqrtf(fmaf(2.0f, w + m, EPS_LOSS));
            if      (m == h0) ++p0;
            else if (m == h1) ++p1;
            else if (m == h2) ++p2;
            else              ++p3;
        }
        int oid = g_sid[b * NPTS + blkq * QPB + t];
        g_loss[b * NPTS + oid] = part;
    }

    // Last-block fixed-order final reduction (proven R11/R12/R15).
    __threadfence();
    __syncthreads();
    if (t == 0) {
        unsigned ticket = atomicAdd(&g_done, 1u);
        last_s = (ticket == NBLK - 1) ? 1 : 0;
    }
    __syncthreads();
    if (last_s) {
        __shared__ float r[TPB];
        float sum = 0.0f;
#pragma unroll
        for (int j = 0; j < NTOT / TPB; ++j) {
            sum += g_loss[j * TPB + t];
        }
        r[t] = sum;
        __syncthreads();
#pragma unroll
        for (int off = TPB / 2; off > 0; off >>= 1) {
            if (t < off) r[t] += r[t + off];
            __syncthreads();
        }
        if (t == 0) {
            out[0] = r[0] * (1.0f / (float)(NTOT * NN_SIZE));
            g_done = 0;
        }
    }
}

extern "C" void kernel_launch(void* const* d_in, const int* in_sizes, int n_in,
                              void* d_out, int out_size) {
    (void)in_sizes; (void)n_in; (void)out_size;
    const float* pts = (const float*)d_in[0];
    float* out = (float*)d_out;

    k_count  <<<(NTOT + 255) / 256, 256>>>(pts);   // idx 0
    k_scanA  <<<BATCH * NSEG, SCAN_T>>>();         // idx 1
    k_scanC  <<<BATCH * NSEG, SCAN_T>>>();         // idx 2
    k_scatter<<<(NTOT + 255) / 256, 256>>>(pts);   // idx 3
    k_main   <<<NBLK, TPB>>>(out);                 // idx 4
}